// round 1
// baseline (speedup 1.0000x reference)
#include <cuda_runtime.h>

// out[m,b] = sum_n M[m,n,b] * V[n,b]
// M: [2048, 2048, 64] f32 (b contiguous), V: [2048, 64] f32, out: [2048, 64] f32
// Pure HBM-streaming kernel: 1 GiB of M read once. Block (16,16) per m-row:
//   threadIdx.x = b-quad (float4 over 64 batch lanes)
//   threadIdx.y = n-slice (strided partition of n, reduced in smem at the end)

#define MV_N     2048
#define MV_MDIM  2048
#define MV_B     64
#define MV_BQ    (MV_B / 4)   // 16 float4 per (m,n) row

__global__ __launch_bounds__(256, 8)
void matvec_batched_kernel(const float4* __restrict__ M4,
                           const float4* __restrict__ V4,
                           float4* __restrict__ out4)
{
    const int m = blockIdx.x;
    const int x = threadIdx.x;   // 0..15, b-quad
    const int y = threadIdx.y;   // 0..15, n-slice

    const float4* Mrow = M4 + (size_t)m * (size_t)(MV_N * MV_BQ);

    float4 acc = make_float4(0.f, 0.f, 0.f, 0.f);

    // Each thread walks n = y, y+16, ... (128 iterations). Unroll for MLP.
    #pragma unroll 8
    for (int n = y; n < MV_N; n += 16) {
        const float4 a = __ldg(&Mrow[n * MV_BQ + x]);
        const float4 v = __ldg(&V4[n * MV_BQ + x]);
        acc.x = fmaf(a.x, v.x, acc.x);
        acc.y = fmaf(a.y, v.y, acc.y);
        acc.z = fmaf(a.z, v.z, acc.z);
        acc.w = fmaf(a.w, v.w, acc.w);
    }

    // Reduce the 16 n-slice partials per b-quad. smem[y][x], tree over y.
    __shared__ float4 red[16][16];
    red[y][x] = acc;
    __syncthreads();

    #pragma unroll
    for (int s = 8; s > 0; s >>= 1) {
        if (y < s) {
            float4 o = red[y + s][x];
            float4 a0 = red[y][x];
            a0.x += o.x; a0.y += o.y; a0.z += o.z; a0.w += o.w;
            red[y][x] = a0;
        }
        __syncthreads();
    }

    if (y == 0) {
        out4[(size_t)m * MV_BQ + x] = red[0][x];
    }
}

extern "C" void kernel_launch(void* const* d_in, const int* in_sizes, int n_in,
                              void* d_out, int out_size)
{
    const float4* M4 = (const float4*)d_in[0];
    const float4* V4 = (const float4*)d_in[1];
    float4* out4 = (float4*)d_out;

    dim3 block(16, 16);
    dim3 grid(MV_MDIM);
    matvec_batched_kernel<<<grid, block>>>(M4, V4, out4);
}